// round 8
// baseline (speedup 1.0000x reference)
#include <cuda_runtime.h>
#include <cuda_bf16.h>

// src [8,16,512,512] f32, flow [8,2,512,512] f32, out [8,16,512,512] f32.
//
// Index math reproduces XLA's lowering bit-exactly (reciprocal-constant rewrite
// of /511, fp32-rounded intermediates, no FMA contraction, rint half-to-even,
// border clamp). Verified rel_err == 0.0 in R3-R7.
//
// R8 structure: shared-memory band staging to eliminate scattered gathers.
//  - CTA = one 16-row output band of one batch image (grid 8*32 = 256).
//  - Per channel: stage 24 src rows (band +/-4 guard) via coalesced float4
//    loads, then resolve the (yi,xi) scatter through the smem crossbar.
//  - Per-pixel local index (dy<<9|xi, fits ushort) computed ONCE, reused x16.
//  - Out-of-band flow (P ~ 7e-6) and nothing else takes an exact global
//    fallback; border clamps provably land in the staged window.

#define B 8
#define C 16
#define H 512
#define W 512
#define HW (H * W)
#define W_BITS 9
#define R 16                 // output rows per CTA
#define G 4                  // guard rows each side
#define SROWS (R + 2 * G)    // 24 staged rows
#define TPB 256
#define PX_PER_CTA (R * W)   // 8192
#define STAGE_FLOATS (SROWS * W)            // 12288
#define SMEM_BYTES (STAGE_FLOATS * 4 + PX_PER_CTA * 2)   // 49152 + 16384 = 65536

__device__ __forceinline__ int ref_index(float coord, float disp)
{
    const float rcp = 1.0f / 511.0f;         // fp32(1/511), XLA recip rewrite
    float t = __fadd_rn(coord, disp);        // ii + flow
    t = __fmul_rn(t, rcp);                   // * (1/511)
    t = __fadd_rn(t, -0.5f);                 // - 0.5
    t = __fmul_rn(2.0f, t);                  // * 2 (exact)
    t = __fadd_rn(t, 1.0f);                  // + 1
    t = __fmul_rn(t, 0.5f);                  // * 0.5 (exact)
    t = __fmul_rn(t, 511.0f);                // * 511
    int i = __float2int_rn(t);               // round half-to-even
    return min(max(i, 0), 511);              // border clamp
}

__global__ __launch_bounds__(TPB, 3) void flow_warp_stage_kernel(
    const float* __restrict__ src,
    const float* __restrict__ flow,
    float* __restrict__ out)
{
    extern __shared__ char smem_raw[];
    float* stage = (float*)smem_raw;                                   // 48 KB
    unsigned short* lin16 = (unsigned short*)(smem_raw + STAGE_FLOATS * 4); // 16 KB

    int bid = blockIdx.x;
    int b   = bid >> 5;                 // 32 bands per image
    int h0  = (bid & 31) * R;
    int ylo = h0 - G;
    int tid = threadIdx.x;

    const float* fb = flow + (size_t)b * 2 * HW;

    // Phase A: per-pixel gather index, computed once, stored as ushort.
    for (int px = tid; px < PX_PER_CTA; px += TPB) {
        int h = h0 + (px >> W_BITS);
        int w = px & (W - 1);
        float f0 = __ldcs(fb + h * W + w);
        float f1 = __ldcs(fb + HW + h * W + w);
        int yi = ref_index((float)h, f0);
        int xi = ref_index((float)w, f1);
        int dy = yi - ylo;
        lin16[px] = ((unsigned)dy < SROWS)
                        ? (unsigned short)((dy << W_BITS) | xi)
                        : (unsigned short)0xFFFF;
    }

    const float* sb_base = src + (size_t)b * C * HW;
    float*       ob_base = out + (size_t)b * C * HW + (size_t)h0 * W;

    for (int c = 0; c < C; ++c) {
        __syncthreads();                       // stage reused across channels
        const float* sb = sb_base + c * HW;

        // Stage 24 rows, coalesced float4 (12 per thread, MLP 12).
        #pragma unroll
        for (int j = 0; j < (STAGE_FLOATS / 4) / TPB; ++j) {   // 12
            int q    = tid + j * TPB;          // float4 id: row*128 + col4
            int row  = q >> 7;
            int ysrc = min(max(ylo + row, 0), H - 1);
            ((float4*)stage)[q] =
                __ldg((const float4*)(sb + ysrc * W) + (q & 127));
        }
        __syncthreads();

        float* ob = ob_base + c * HW;
        #pragma unroll 8
        for (int px = tid; px < PX_PER_CTA; px += TPB) {
            unsigned short u = lin16[px];
            float val;
            if (u != 0xFFFF) {
                val = stage[u];                // smem crossbar handles scatter
            } else {                           // rare (~1e-5): exact global path
                int h = h0 + (px >> W_BITS);
                int w = px & (W - 1);
                float f0 = __ldg(fb + h * W + w);
                float f1 = __ldg(fb + HW + h * W + w);
                int yi = ref_index((float)h, f0);
                int xi = ref_index((float)w, f1);
                val = __ldg(sb + yi * W + xi);
            }
            __stcs(ob + px, val);              // coalesced, evict-first
        }
    }
}

extern "C" void kernel_launch(void* const* d_in, const int* in_sizes, int n_in,
                              void* d_out, int out_size)
{
    const float* src  = (const float*)d_in[0];
    const float* flow = (const float*)d_in[1];
    float*       out  = (float*)d_out;

    cudaFuncSetAttribute(flow_warp_stage_kernel,
                         cudaFuncAttributeMaxDynamicSharedMemorySize, SMEM_BYTES);

    int blocks = B * (H / R);           // 256 CTAs, all co-resident
    flow_warp_stage_kernel<<<blocks, TPB, SMEM_BYTES>>>(src, flow, out);
}